// round 9
// baseline (speedup 1.0000x reference)
#include <cuda_runtime.h>
#include <cuda_bf16.h>

#define N_NODES    50000
#define N_EDGES    800000
#define IN_DIM     128
#define HID_DIM    64
#define OUT_DIM    64
#define NUM_GRAPHS 512
#define SCAN_T     1024

// ---------------- scratch (device globals; no allocations allowed) ----------------
__device__ __align__(16) int    g_degc  [N_NODES];        // per-dst edge count (int)
__device__ __align__(16) int    g_cur   [N_NODES];        // fill cursor (int)
__device__ __align__(16) int    g_row   [N_NODES + 1];    // CSR row offsets
__device__ __align__(16) float  g_dinv  [N_NODES];
__device__ __align__(16) float2 g_csr   [N_EDGES];        // {src (int bits), norm}
__device__ __align__(16) int    g_gstart[NUM_GRAPHS + 1]; // graph segment boundaries
__device__ __align__(16) float  g_h     [N_NODES * 64];   // GEMM output (both layers)
__device__ __align__(16) float  g_agg1  [N_NODES * 64];   // relu(agg) layer 1
__device__ __align__(16) float  g_agg2  [N_NODES * 64];   // relu(agg) layer 2

// ---------------- kernels ----------------
__global__ void __launch_bounds__(256) zero_kernel() {
    int i = blockIdx.x * blockDim.x + threadIdx.x;
    if (i < N_NODES) { g_degc[i] = 0; g_cur[i] = 0; }
}

// count edges per dst (int atomics only).  Indices are INT32 (JAX default x64-off).
__global__ void __launch_bounds__(256) count_kernel(const int* __restrict__ ei) {
    int e = blockIdx.x * blockDim.x + threadIdx.x;
    if (e >= N_EDGES) return;
    atomicAdd(&g_degc[ei[N_EDGES + e]], 1);
}

// single-block exclusive scan of g_degc -> g_row
__global__ void __launch_bounds__(SCAN_T) scan_kernel() {
    __shared__ int sp[SCAN_T];
    int t = threadIdx.x;
    const int C = (N_NODES + SCAN_T - 1) / SCAN_T;   // 49
    int beg = t * C;
    int end = min(beg + C, N_NODES);
    int sum = 0;
    for (int i = beg; i < end; i++) sum += g_degc[i];
    sp[t] = sum;
    __syncthreads();
    // Hillis-Steele inclusive scan
    for (int off = 1; off < SCAN_T; off <<= 1) {
        int v = (t >= off) ? sp[t - off] : 0;
        __syncthreads();
        sp[t] += v;
        __syncthreads();
    }
    int excl = sp[t] - sum;
    for (int i = beg; i < end; i++) {
        g_row[i] = excl;
        excl += g_degc[i];
    }
    if (t == SCAN_T - 1) g_row[N_NODES] = sp[SCAN_T - 1];
}

// per-node: dinv = rsqrt(max(deg,1)); graph boundaries from sorted batch
__global__ void __launch_bounds__(256) node_kernel(const int* __restrict__ batch) {
    int n = blockIdx.x * blockDim.x + threadIdx.x;
    if (n >= N_NODES) return;
    g_dinv[n] = rsqrtf(fmaxf((float)g_degc[n], 1.0f));
    int b  = batch[n];
    int bp = (n == 0) ? -1 : batch[n - 1];
    for (int g = bp + 1; g <= b; g++) g_gstart[g] = n;
    if (n == N_NODES - 1)
        for (int g = b + 1; g <= NUM_GRAPHS; g++) g_gstart[g] = N_NODES;
}

// counting-sort fill: CSR entry = {src bits, dinv[src]*dinv[dst]}
__global__ void __launch_bounds__(256) fill_kernel(const int* __restrict__ ei) {
    int e = blockIdx.x * blockDim.x + threadIdx.x;
    if (e >= N_EDGES) return;
    int s = ei[e];
    int d = ei[N_EDGES + e];
    int pos = g_row[d] + atomicAdd(&g_cur[d], 1);
    g_csr[pos] = make_float2(__int_as_float(s), g_dinv[s] * g_dinv[d]);
}

// GEMM: g_h[M,64] = A[M,KTOT] @ W[KTOT,64] + bias
// A_IS_AGG1: read g_agg1 (already relu'd) instead of param A.
template<int KTOT, bool A_IS_AGG1>
__global__ void __launch_bounds__(256) gemm_kernel(const float* __restrict__ Ap,
                                                   const float* __restrict__ W,
                                                   const float* __restrict__ bias) {
    __shared__ float sA[64 * 68];   // padded stride -> conflict-free column reads
    __shared__ float sW[64 * 64];

    const float* A = A_IS_AGG1 ? g_agg1 : Ap;
    int tid  = threadIdx.x;
    int row0 = blockIdx.x * 64;
    int ty   = tid >> 4;     // 0..15
    int tx   = tid & 15;     // 0..15

    float acc[4][4];
#pragma unroll
    for (int i = 0; i < 4; i++)
#pragma unroll
        for (int j = 0; j < 4; j++) acc[i][j] = 0.f;

    for (int k0 = 0; k0 < KTOT; k0 += 64) {
#pragma unroll
        for (int t = tid; t < 64 * 16; t += 256) {
            int r  = t >> 4;
            int kc = t & 15;
            float4 v = make_float4(0.f, 0.f, 0.f, 0.f);
            int gr = row0 + r;
            if (gr < N_NODES)
                v = *(const float4*)(A + (size_t)gr * KTOT + k0 + kc * 4);
            *(float4*)(sA + r * 68 + kc * 4) = v;
        }
#pragma unroll
        for (int t = tid; t < 64 * 16; t += 256) {
            int kr = t >> 4;
            int cc = t & 15;
            *(float4*)(sW + kr * 64 + cc * 4) =
                *(const float4*)(W + (size_t)(k0 + kr) * 64 + cc * 4);
        }
        __syncthreads();

#pragma unroll
        for (int k = 0; k < 64; k++) {
            float a0 = sA[(ty * 4 + 0) * 68 + k];
            float a1 = sA[(ty * 4 + 1) * 68 + k];
            float a2 = sA[(ty * 4 + 2) * 68 + k];
            float a3 = sA[(ty * 4 + 3) * 68 + k];
            float4 w = *(const float4*)(sW + k * 64 + tx * 4);
            acc[0][0] += a0 * w.x; acc[0][1] += a0 * w.y; acc[0][2] += a0 * w.z; acc[0][3] += a0 * w.w;
            acc[1][0] += a1 * w.x; acc[1][1] += a1 * w.y; acc[1][2] += a1 * w.z; acc[1][3] += a1 * w.w;
            acc[2][0] += a2 * w.x; acc[2][1] += a2 * w.y; acc[2][2] += a2 * w.z; acc[2][3] += a2 * w.w;
            acc[3][0] += a3 * w.x; acc[3][1] += a3 * w.y; acc[3][2] += a3 * w.z; acc[3][3] += a3 * w.w;
        }
        __syncthreads();
    }

    float4 bv = *(const float4*)(bias + tx * 4);
#pragma unroll
    for (int i = 0; i < 4; i++) {
        int gr = row0 + ty * 4 + i;
        if (gr < N_NODES) {
            float4 o = make_float4(acc[i][0] + bv.x, acc[i][1] + bv.y,
                                   acc[i][2] + bv.z, acc[i][3] + bv.w);
            *(float4*)(g_h + (size_t)gr * 64 + tx * 4) = o;
        }
    }
}

// pull aggregation: one warp per node; lane owns 2 dims.
// agg[n] = relu( sum_{e in CSR[n]} h[src_e] * w_e ).  No atomics.
template<bool TO_AGG2>
__global__ void __launch_bounds__(256) agg_kernel() {
    int gw   = (blockIdx.x * 256 + threadIdx.x) >> 5;   // global warp id = node
    int lane = threadIdx.x & 31;
    if (gw >= N_NODES) return;
    int s0 = g_row[gw];
    int s1 = g_row[gw + 1];

    float2 acc0 = make_float2(0.f, 0.f);
    float2 acc1 = make_float2(0.f, 0.f);
    int e = s0;
    for (; e + 1 < s1; e += 2) {
        float2 m0 = g_csr[e];
        float2 m1 = g_csr[e + 1];
        int src0 = __float_as_int(m0.x);
        int src1 = __float_as_int(m1.x);
        float2 v0 = *(const float2*)(g_h + (size_t)src0 * 64 + lane * 2);
        float2 v1 = *(const float2*)(g_h + (size_t)src1 * 64 + lane * 2);
        acc0.x += v0.x * m0.y; acc0.y += v0.y * m0.y;
        acc1.x += v1.x * m1.y; acc1.y += v1.y * m1.y;
    }
    if (e < s1) {
        float2 m0 = g_csr[e];
        int src0 = __float_as_int(m0.x);
        float2 v0 = *(const float2*)(g_h + (size_t)src0 * 64 + lane * 2);
        acc0.x += v0.x * m0.y; acc0.y += v0.y * m0.y;
    }
    float2 r = make_float2(fmaxf(acc0.x + acc1.x, 0.f),
                           fmaxf(acc0.y + acc1.y, 0.f));
    float* dst = TO_AGG2 ? g_agg2 : g_agg1;
    *(float2*)(dst + (size_t)gw * 64 + lane * 2) = r;
}

// pooling: one block per graph over its contiguous node range; mean of g_agg2.
__global__ void __launch_bounds__(256) pool_kernel(float* __restrict__ out) {
    __shared__ float sm[256];
    int g = blockIdx.x;
    int t = threadIdx.x;
    int d = t & 63;
    int r = t >> 6;        // 0..3
    int s0 = g_gstart[g];
    int s1 = g_gstart[g + 1];
    float acc = 0.f;
    for (int n = s0 + r; n < s1; n += 4)
        acc += g_agg2[(size_t)n * 64 + d];
    sm[t] = acc;
    __syncthreads();
    if (t < 64) {
        float v = sm[t] + sm[t + 64] + sm[t + 128] + sm[t + 192];
        float c = (float)(s1 - s0);
        out[(size_t)g * 64 + t] = v / fmaxf(c, 1.0f);
    }
}

// ---------------- launch ----------------
extern "C" void kernel_launch(void* const* d_in, const int* in_sizes, int n_in,
                              void* d_out, int out_size) {
    // Identify inputs by element count (robust to metadata ordering).
    // x: 6.4M f32 | edge_index: 1.6M i32 | batch: 50000 i32
    // W1: 8192 f32 | b1: 64 f32 | W2: 4096 f32 | b2: 64 f32 (b1 before b2)
    const float *x = nullptr, *W1 = nullptr, *b1 = nullptr, *W2 = nullptr, *b2 = nullptr;
    const int   *ei = nullptr, *batch = nullptr;
    for (int i = 0; i < n_in; i++) {
        switch (in_sizes[i]) {
            case N_NODES * IN_DIM:   x     = (const float*)d_in[i]; break;
            case 2 * N_EDGES:        ei    = (const int*)d_in[i];   break;
            case N_NODES:            batch = (const int*)d_in[i];   break;
            case IN_DIM * HID_DIM:   W1    = (const float*)d_in[i]; break;
            case HID_DIM * OUT_DIM:  W2    = (const float*)d_in[i]; break;
            case HID_DIM:
                if (!b1) b1 = (const float*)d_in[i];
                else     b2 = (const float*)d_in[i];
                break;
            default: break;
        }
    }
    float* out = (float*)d_out;

    const int T = 256;
    zero_kernel <<<(N_NODES + T - 1) / T, T>>>();
    count_kernel<<<(N_EDGES + T - 1) / T, T>>>(ei);
    scan_kernel <<<1, SCAN_T>>>();
    node_kernel <<<(N_NODES + T - 1) / T, T>>>(batch);
    fill_kernel <<<(N_EDGES + T - 1) / T, T>>>(ei);

    // layer 1: h = x @ W1 + b1; agg1 = relu(pull-agg(h))
    gemm_kernel<IN_DIM, false><<<(N_NODES + 63) / 64, T>>>(x, W1, b1);
    agg_kernel<false><<<(N_NODES * 32 + T - 1) / T, T>>>();

    // layer 2: h = agg1 @ W2 + b2; agg2 = relu(pull-agg(h))
    gemm_kernel<HID_DIM, true><<<(N_NODES + 63) / 64, T>>>(nullptr, W2, b2);
    agg_kernel<true><<<(N_NODES * 32 + T - 1) / T, T>>>();

    // pooling: mean over each graph's contiguous node segment
    pool_kernel<<<NUM_GRAPHS, T>>>(out);
}